// round 1
// baseline (speedup 1.0000x reference)
#include <cuda_runtime.h>

#define Bz 8
#define Nn 65536
#define Ee 32
#define Kk 33
#define BPB 128            // blocks per batch
#define PPB (Nn / BPB)     // 512 points per block
#define T1 256
#define W1 (T1 / 32)

#define DELTA_V 0.5f
#define DELTA_D 1.5f
#define GAMMA 0.001f
#define EPSX 1e-12f

// Scratch (allocation-free rule: __device__ globals)
__device__ float g_sums[Bz * Kk * Ee];
__device__ float g_counts[Bz * Kk];
__device__ float g_hinge[Bz * Kk];

// ---------------------------------------------------------------------------
// Zero all scratch + output scalar
// ---------------------------------------------------------------------------
__global__ void zero_kernel(float* out) {
    int i = blockIdx.x * blockDim.x + threadIdx.x;
    if (i < Bz * Kk * Ee) g_sums[i] = 0.f;
    if (i < Bz * Kk) { g_counts[i] = 0.f; g_hinge[i] = 0.f; }
    if (i == 0) out[0] = 0.f;
}

// ---------------------------------------------------------------------------
// Pass 1: per-(b,k) embedding sums + counts.
// Warp-per-point; per-warp PRIVATE shared accumulators (no shared atomics in
// the hot loop: within one warp instruction all lanes share the point's label,
// so addresses k*32+lane are distinct & conflict-free; cross-iteration order
// is guaranteed by per-thread shared-memory program order).
// ---------------------------------------------------------------------------
__global__ void __launch_bounds__(T1) pass1_kernel(const float* __restrict__ emb,
                                                   const int* __restrict__ lab) {
    __shared__ float s_sum[W1][Kk * Ee];
    __shared__ float s_cnt[W1][Kk];

    int tid = threadIdx.x;
    int w = tid >> 5;
    int lane = tid & 31;

    for (int i = lane; i < Kk * Ee; i += 32) s_sum[w][i] = 0.f;
    for (int i = lane; i < Kk; i += 32) s_cnt[w][i] = 0.f;
    __syncwarp();

    int b = blockIdx.x / BPB;
    int base = b * Nn + (blockIdx.x % BPB) * PPB;

    for (int p = w; p < PPB; p += W1) {
        int gp = base + p;
        float x = emb[gp * Ee + lane];   // coalesced 128B
        int k = lab[gp];                 // broadcast load
        s_sum[w][k * Ee + lane] += x;    // LDS+FADD+STS, race-free
        if (lane == 0) s_cnt[w][k] += 1.f;
    }
    __syncthreads();

    // merge warp copies -> global (spread atomics, cheap)
    for (int i = tid; i < Kk * Ee; i += T1) {
        float s = 0.f;
#pragma unroll
        for (int ww = 0; ww < W1; ww++) s += s_sum[ww][i];
        atomicAdd(&g_sums[b * Kk * Ee + i], s);
    }
    for (int i = tid; i < Kk; i += T1) {
        float s = 0.f;
#pragma unroll
        for (int ww = 0; ww < W1; ww++) s += s_cnt[ww][i];
        atomicAdd(&g_counts[b * Kk + i], s);
    }
}

// ---------------------------------------------------------------------------
// Pass 2: per-point hinge(||x - c_label|| - delta_v), summed per (b,k).
// Centers cached in shared; per-warp private hinge bins (lane 0 only writes).
// ---------------------------------------------------------------------------
__global__ void __launch_bounds__(T1) pass2_kernel(const float* __restrict__ emb,
                                                   const int* __restrict__ lab) {
    __shared__ float s_c[Kk * Ee];
    __shared__ float s_h[W1][Kk];

    int tid = threadIdx.x;
    int w = tid >> 5;
    int lane = tid & 31;
    int b = blockIdx.x / BPB;

    for (int i = tid; i < Kk * Ee; i += T1) {
        float cnt = g_counts[b * Kk + (i >> 5)];   // i>>5 == i/Ee (Ee==32)
        s_c[i] = g_sums[b * Kk * Ee + i] / fmaxf(cnt, 1.f);
    }
    for (int i = lane; i < Kk; i += 32) s_h[w][i] = 0.f;
    __syncthreads();

    int base = b * Nn + (blockIdx.x % BPB) * PPB;

    for (int p = w; p < PPB; p += W1) {
        int gp = base + p;
        float x = emb[gp * Ee + lane];
        int k = lab[gp];
        float d = x - s_c[k * Ee + lane];
        float d2 = d * d;
#pragma unroll
        for (int off = 16; off; off >>= 1)
            d2 += __shfl_xor_sync(0xFFFFFFFFu, d2, off);
        if (lane == 0 && k > 0) {
            float dist = sqrtf(fmaxf(d2, EPSX));
            float h = dist - DELTA_V;
            if (h > 0.f) s_h[w][k] += h;
        }
    }
    __syncthreads();

    for (int i = tid; i < Kk; i += T1) {
        float s = 0.f;
#pragma unroll
        for (int ww = 0; ww < W1; ww++) s += s_h[ww][i];
        atomicAdd(&g_hinge[b * Kk + i], s);
    }
}

// ---------------------------------------------------------------------------
// Pass 3: per-batch finalize (variance / pairwise-distance / reg terms).
// One block per batch; all work is over K=33 instances (tiny).
// ---------------------------------------------------------------------------
__global__ void __launch_bounds__(256) pass3_kernel(float* out) {
    __shared__ float s_c[Kk * Ee];
    __shared__ float s_cnt[Kk];
    __shared__ float acc_pair, acc_var, acc_reg, s_ninst;

    int b = blockIdx.x;
    int tid = threadIdx.x;

    for (int i = tid; i < Kk * Ee; i += blockDim.x) {
        float cnt = g_counts[b * Kk + (i >> 5)];
        s_c[i] = g_sums[b * Kk * Ee + i] / fmaxf(cnt, 1.f);
    }
    if (tid < Kk) s_cnt[tid] = g_counts[b * Kk + tid];
    if (tid == 0) { acc_pair = 0.f; acc_var = 0.f; acc_reg = 0.f; }
    __syncthreads();

    if (tid == 0) {
        float ni = 0.f;
        for (int k = 1; k < Kk; k++) ni += (s_cnt[k] > 0.f) ? 1.f : 0.f;
        s_ninst = ni;
    }

    // variance + reg terms: thread per instance k (k=0 excluded: present[:,0]=False)
    if (tid >= 1 && tid < Kk) {
        int k = tid;
        if (s_cnt[k] > 0.f) {
            float v = g_hinge[b * Kk + k] / fmaxf(s_cnt[k], 1.f);
            float n2 = 0.f;
            for (int e = 0; e < Ee; e++) { float c = s_c[k * Ee + e]; n2 += c * c; }
            atomicAdd(&acc_var, v);
            atomicAdd(&acc_reg, sqrtf(fmaxf(n2, EPSX)));
        }
    }

    // pairwise hinge over upper triangle of present instances
    for (int pi = tid; pi < Kk * Kk; pi += blockDim.x) {
        int i = pi / Kk, j = pi % Kk;
        if (i < 1 || j <= i) continue;          // present excludes k=0; j>i
        if (s_cnt[i] > 0.f && s_cnt[j] > 0.f) {
            float d2 = 0.f;
            for (int e = 0; e < Ee; e++) {
                float d = s_c[i * Ee + e] - s_c[j * Ee + e];
                d2 += d * d;
            }
            float cd = sqrtf(fmaxf(d2, EPSX));
            float ph = fmaxf(2.f * DELTA_D - cd, 0.f);
            atomicAdd(&acc_pair, ph);
        }
    }
    __syncthreads();

    if (tid == 0) {
        float ni = s_ninst;
        float var_t = acc_var / fmaxf(ni, 1.f);
        float npairs = ni * (ni - 1.f) * 0.5f;
        float dist_t = acc_pair / fmaxf(npairs, 1.f);
        float reg_t = acc_reg / fmaxf(ni, 1.f);
        float pb = var_t + dist_t + GAMMA * reg_t;
        if (!(ni > 0.f)) pb = 0.f;
        atomicAdd(out, pb / (float)Bz);
    }
}

// ---------------------------------------------------------------------------
extern "C" void kernel_launch(void* const* d_in, const int* in_sizes, int n_in,
                              void* d_out, int out_size) {
    const float* emb = (const float*)d_in[0];
    const int* lab = (const int*)d_in[1];
    float* out = (float*)d_out;

    zero_kernel<<<(Bz * Kk * Ee + 255) / 256, 256>>>(out);
    pass1_kernel<<<Bz * BPB, T1>>>(emb, lab);
    pass2_kernel<<<Bz * BPB, T1>>>(emb, lab);
    pass3_kernel<<<Bz, 256>>>(out);
}

// round 2
// speedup vs baseline: 1.5613x; 1.5613x over previous
#include <cuda_runtime.h>

#define Bz 8
#define Nn 65536
#define Ee 32
#define Kk 33
#define BPB 128            // blocks per batch
#define PPB (Nn / BPB)     // 512 points per block
#define T1 256
#define W1 (T1 / 32)

#define DELTA_V 0.5f
#define DELTA_D 1.5f
#define GAMMA 0.001f
#define EPSX 1e-12f

#define FULLM 0xFFFFFFFFu

// Scratch (allocation-free rule: __device__ globals)
__device__ float4 g_sums4[Bz * Kk * 8];   // [b][k][e/4] (flat float == [b][k][e])
__device__ float  g_counts[Bz * Kk];
__device__ float  g_hinge[Bz * Kk];
__device__ int    g_ctr[Bz];

// ---------------------------------------------------------------------------
// Zero all scratch + output scalar (single tiny block)
// ---------------------------------------------------------------------------
__global__ void zero_kernel(float* out) {
    int i = threadIdx.x;
    for (int j = i; j < Bz * Kk * 8; j += blockDim.x)
        g_sums4[j] = make_float4(0.f, 0.f, 0.f, 0.f);
    if (i < Bz * Kk) { g_counts[i] = 0.f; g_hinge[i] = 0.f; }
    if (i < Bz) g_ctr[i] = 0;
    if (i == 0) out[0] = 0.f;
}

// ---------------------------------------------------------------------------
// Pass 1: per-(b,k) embedding sums + counts.
// float4 / 8-lanes-per-point: each warp instruction covers 4 points.
// Per-warp PRIVATE shared accumulators; label-collision among the 4 points of
// a warp-iter handled by warp-uniform fallback serialization.
// ---------------------------------------------------------------------------
__global__ void __launch_bounds__(T1) pass1_kernel(const float4* __restrict__ emb4,
                                                   const int* __restrict__ lab) {
    __shared__ float4 s_sum[W1][Kk * 8];
    __shared__ float  s_cnt[W1][Kk];

    int tid = threadIdx.x;
    int w = tid >> 5;
    int lane = tid & 31;
    int sub = lane >> 3;     // which of 4 points in this warp-iter
    int l8  = lane & 7;      // float4 slot within the point (e = l8*4 + c)

    for (int i = lane; i < Kk * 8; i += 32) s_sum[w][i] = make_float4(0.f, 0.f, 0.f, 0.f);
    for (int i = lane; i < Kk; i += 32) s_cnt[w][i] = 0.f;
    __syncwarp();

    int b = blockIdx.x / BPB;
    int base = b * Nn + (blockIdx.x % BPB) * PPB;

    for (int p0 = w * 4; p0 < PPB; p0 += W1 * 4) {
        int gp = base + p0 + sub;
        float4 v = emb4[(size_t)gp * 8 + l8];       // 512B contiguous per warp
        int k = lab[gp];

        unsigned m = __match_any_sync(FULLM, k);    // whole-subgroup granularity
        bool all_distinct = __all_sync(FULLM, __popc(m) == 8);
        int idx = k * 8 + l8;

        if (all_distinct) {                         // ~83% of warp-iters
            float4 a = s_sum[w][idx];
            a.x += v.x; a.y += v.y; a.z += v.z; a.w += v.w;
            s_sum[w][idx] = a;
            if (l8 == 0) s_cnt[w][k] += 1.f;
        } else {                                    // serialize the 4 points
#pragma unroll
            for (int s = 0; s < 4; s++) {
                if (sub == s) {
                    float4 a = s_sum[w][idx];
                    a.x += v.x; a.y += v.y; a.z += v.z; a.w += v.w;
                    s_sum[w][idx] = a;
                    if (l8 == 0) s_cnt[w][k] += 1.f;
                }
                __syncwarp();
            }
        }
        __syncwarp();   // order cross-lane shared RMW across iterations
    }
    __syncthreads();

    // merge warp copies -> global (spread atomics over 8448 addrs, cheap)
    const float* flat[W1];
#pragma unroll
    for (int ww = 0; ww < W1; ww++) flat[ww] = (const float*)s_sum[ww];
    float* gs = (float*)g_sums4;
    for (int i = tid; i < Kk * Ee; i += T1) {
        float s = 0.f;
#pragma unroll
        for (int ww = 0; ww < W1; ww++) s += flat[ww][i];
        atomicAdd(gs + b * Kk * Ee + i, s);
    }
    for (int i = tid; i < Kk; i += T1) {
        float s = 0.f;
#pragma unroll
        for (int ww = 0; ww < W1; ww++) s += s_cnt[ww][i];
        atomicAdd(&g_counts[b * Kk + i], s);
    }
}

// ---------------------------------------------------------------------------
// Pass 2: per-point hinge(||x - c_label|| - delta_v), summed per (b,k);
// last block of each batch runs the K=33 finalize and adds into out.
// ---------------------------------------------------------------------------
__global__ void __launch_bounds__(T1) pass2_kernel(const float4* __restrict__ emb4,
                                                   const int* __restrict__ lab,
                                                   float* __restrict__ out) {
    __shared__ float4 s_c[Kk * 8];
    __shared__ float  s_h[W1][Kk];
    __shared__ float  s_cnt[Kk];
    __shared__ float  red[3][W1];
    __shared__ int    s_flag;

    int tid = threadIdx.x;
    int w = tid >> 5;
    int lane = tid & 31;
    int sub = lane >> 3;
    int l8  = lane & 7;
    int b = blockIdx.x / BPB;

    for (int i = tid; i < Kk * 8; i += T1) {
        float cnt = g_counts[b * Kk + (i >> 3)];
        float inv = 1.f / fmaxf(cnt, 1.f);
        float4 s = g_sums4[b * Kk * 8 + i];
        s_c[i] = make_float4(s.x * inv, s.y * inv, s.z * inv, s.w * inv);
    }
    if (tid < Kk) s_cnt[tid] = g_counts[b * Kk + tid];
    for (int i = lane; i < Kk; i += 32) s_h[w][i] = 0.f;
    __syncthreads();

    int base = b * Nn + (blockIdx.x % BPB) * PPB;

    for (int p0 = w * 4; p0 < PPB; p0 += W1 * 4) {
        int gp = base + p0 + sub;
        float4 v = emb4[(size_t)gp * 8 + l8];
        int k = lab[gp];
        float4 c = s_c[k * 8 + l8];
        float dx = v.x - c.x, dy = v.y - c.y, dz = v.z - c.z, dw = v.w - c.w;
        float d2 = dx * dx + dy * dy + dz * dz + dw * dw;
        d2 += __shfl_xor_sync(FULLM, d2, 1);
        d2 += __shfl_xor_sync(FULLM, d2, 2);
        d2 += __shfl_xor_sync(FULLM, d2, 4);
        if (l8 == 0 && k > 0) {
            float h = sqrtf(fmaxf(d2, EPSX)) - DELTA_V;
            if (h > 0.f) atomicAdd(&s_h[w][k], h);   // <=4 lanes, mostly spread
        }
    }
    __syncthreads();

    for (int i = tid; i < Kk; i += T1) {
        float s = 0.f;
#pragma unroll
        for (int ww = 0; ww < W1; ww++) s += s_h[ww][i];
        atomicAdd(&g_hinge[b * Kk + i], s);
    }

    // ---- last-block-done: finalize batch b ----
    __threadfence();            // release our g_hinge contributions
    __syncthreads();
    if (tid == 0) {
        int done = atomicAdd(&g_ctr[b], 1);
        s_flag = (done == BPB - 1) ? 1 : 0;
    }
    __syncthreads();
    if (!s_flag) return;
    __threadfence();            // acquire: all blocks' g_hinge now visible

    // centers already in s_c, counts in s_cnt
    float var_acc = 0.f, reg_acc = 0.f, pair_acc = 0.f;

    if (tid >= 1 && tid < Kk && s_cnt[tid] > 0.f) {
        int k = tid;
        var_acc = g_hinge[b * Kk + k] / s_cnt[k];
        float n2 = 0.f;
#pragma unroll
        for (int j = 0; j < 8; j++) {
            float4 c = s_c[k * 8 + j];
            n2 += c.x * c.x + c.y * c.y + c.z * c.z + c.w * c.w;
        }
        reg_acc = sqrtf(fmaxf(n2, EPSX));
    }

    for (int pi = tid; pi < Kk * Kk; pi += T1) {
        int i = pi / Kk, j = pi % Kk;
        if (i >= 1 && j > i && s_cnt[i] > 0.f && s_cnt[j] > 0.f) {
            float d2 = 0.f;
#pragma unroll
            for (int e = 0; e < 8; e++) {
                float4 a = s_c[i * 8 + e], bb = s_c[j * 8 + e];
                float ex = a.x - bb.x, ey = a.y - bb.y, ez = a.z - bb.z, ew = a.w - bb.w;
                d2 += ex * ex + ey * ey + ez * ez + ew * ew;
            }
            float cd = sqrtf(fmaxf(d2, EPSX));
            pair_acc += fmaxf(2.f * DELTA_D - cd, 0.f);
        }
    }

    // block reduce the three accumulators (shuffle + shared)
#pragma unroll
    for (int off = 16; off; off >>= 1) {
        var_acc  += __shfl_xor_sync(FULLM, var_acc, off);
        reg_acc  += __shfl_xor_sync(FULLM, reg_acc, off);
        pair_acc += __shfl_xor_sync(FULLM, pair_acc, off);
    }
    if (lane == 0) { red[0][w] = var_acc; red[1][w] = reg_acc; red[2][w] = pair_acc; }
    __syncthreads();

    if (tid == 0) {
        float var_s = 0.f, reg_s = 0.f, pair_s = 0.f;
#pragma unroll
        for (int ww = 0; ww < W1; ww++) {
            var_s += red[0][ww]; reg_s += red[1][ww]; pair_s += red[2][ww];
        }
        float ni = 0.f;
        for (int k = 1; k < Kk; k++) ni += (s_cnt[k] > 0.f) ? 1.f : 0.f;
        float var_t = var_s / fmaxf(ni, 1.f);
        float npairs = ni * (ni - 1.f) * 0.5f;
        float dist_t = pair_s / fmaxf(npairs, 1.f);
        float reg_t = reg_s / fmaxf(ni, 1.f);
        float pb = var_t + dist_t + GAMMA * reg_t;
        if (!(ni > 0.f)) pb = 0.f;
        atomicAdd(out, pb / (float)Bz);
    }
}

// ---------------------------------------------------------------------------
extern "C" void kernel_launch(void* const* d_in, const int* in_sizes, int n_in,
                              void* d_out, int out_size) {
    const float4* emb4 = (const float4*)d_in[0];
    const int* lab = (const int*)d_in[1];
    float* out = (float*)d_out;

    zero_kernel<<<1, 1024>>>(out);
    pass1_kernel<<<Bz * BPB, T1>>>(emb4, lab);
    pass2_kernel<<<Bz * BPB, T1>>>(emb4, lab, out);
}

// round 6
// speedup vs baseline: 1.9001x; 1.2170x over previous
#include <cuda_runtime.h>

#define Bz 8
#define Nn 65536
#define Ee 32
#define Kk 33
#define BPB 128            // blocks per batch
#define PPB (Nn / BPB)     // 512 points per block
#define T1 256
#define W1 (T1 / 32)

#define DELTA_V 0.5f
#define DELTA_D 1.5f
#define GAMMA 0.001f
#define EPSX 1e-12f

#define FULLM 0xFFFFFFFFu

// Scratch (allocation-free rule: __device__ globals, zero-init at load;
// self-cleaned at end of each run so graph replays stay deterministic).
__device__ float4 g_sums4[Bz * Kk * 8];   // [b][k][e/4]
__device__ float  g_counts[Bz * Kk];
__device__ float  g_hinge[Bz * Kk];
__device__ int    g_ctr[Bz];

// ---------------------------------------------------------------------------
// Pass 1: per-(b,k) embedding sums + counts.
// float4 / 8-lanes-per-point, unroll-2 (8 points per warp-iter, 2 front-batched
// LDG.128s for MLP). Per-warp PRIVATE shared accumulators; label collisions
// among the 4 points of a half handled by warp-uniform serialization.
// ---------------------------------------------------------------------------
__global__ void __launch_bounds__(T1) pass1_kernel(const float4* __restrict__ emb4,
                                                   const int* __restrict__ lab,
                                                   float* __restrict__ out) {
    __shared__ float4 s_sum[W1][Kk * 8];
    __shared__ float  s_cnt[W1][Kk];

    int tid = threadIdx.x;
    int w = tid >> 5;
    int lane = tid & 31;
    int sub = lane >> 3;     // which of 4 points in a half
    int l8  = lane & 7;      // float4 slot within the point

    if (blockIdx.x == 0 && tid == 0) out[0] = 0.f;   // ordered before pass2

    for (int i = lane; i < Kk * 8; i += 32) s_sum[w][i] = make_float4(0.f, 0.f, 0.f, 0.f);
    for (int i = lane; i < Kk; i += 32) s_cnt[w][i] = 0.f;
    __syncwarp();

    int b = blockIdx.x / BPB;
    int base = b * Nn + (blockIdx.x % BPB) * PPB;

    for (int p0 = w * 8; p0 < PPB; p0 += W1 * 8) {
        int gp0 = base + p0 + sub;
        int gp1 = gp0 + 4;
        // front-batched loads (MLP = 2x128B + labels)
        float4 v0 = emb4[(size_t)gp0 * 8 + l8];
        float4 v1 = emb4[(size_t)gp1 * 8 + l8];
        int k0 = lab[gp0];
        int k1 = lab[gp1];

#pragma unroll
        for (int h = 0; h < 2; h++) {
            float4 v = h ? v1 : v0;
            int k = h ? k1 : k0;
            unsigned m = __match_any_sync(FULLM, k);
            bool all_distinct = __all_sync(FULLM, __popc(m) == 8);
            int idx = k * 8 + l8;
            if (all_distinct) {                     // ~83% of halves
                float4 a = s_sum[w][idx];
                a.x += v.x; a.y += v.y; a.z += v.z; a.w += v.w;
                s_sum[w][idx] = a;
                if (l8 == 0) s_cnt[w][k] += 1.f;
            } else {                                // serialize the 4 points
#pragma unroll
                for (int s = 0; s < 4; s++) {
                    if (sub == s) {
                        float4 a = s_sum[w][idx];
                        a.x += v.x; a.y += v.y; a.z += v.z; a.w += v.w;
                        s_sum[w][idx] = a;
                        if (l8 == 0) s_cnt[w][k] += 1.f;
                    }
                    __syncwarp();
                }
            }
            __syncwarp();   // order cross-lane shared RMW between halves/iters
        }
    }
    __syncthreads();

    // merge warp copies -> global (spread atomics over 8448 addrs, cheap)
    const float* flat[W1];
#pragma unroll
    for (int ww = 0; ww < W1; ww++) flat[ww] = (const float*)s_sum[ww];
    float* gs = (float*)g_sums4;
    for (int i = tid; i < Kk * Ee; i += T1) {
        float s = 0.f;
#pragma unroll
        for (int ww = 0; ww < W1; ww++) s += flat[ww][i];
        atomicAdd(gs + b * Kk * Ee + i, s);
    }
    for (int i = tid; i < Kk; i += T1) {
        float s = 0.f;
#pragma unroll
        for (int ww = 0; ww < W1; ww++) s += s_cnt[ww][i];
        atomicAdd(&g_counts[b * Kk + i], s);
    }
}

// ---------------------------------------------------------------------------
// Pass 2: per-point hinge(||x - c_label|| - delta_v), summed per (b,k);
// unroll-4 (16 points per warp-iter, 4 front-batched LDG.128s).
// Last block of each batch runs the K=33 finalize, adds into out, and
// re-zeroes this batch's scratch for the next graph replay.
// ---------------------------------------------------------------------------
__global__ void __launch_bounds__(T1) pass2_kernel(const float4* __restrict__ emb4,
                                                   const int* __restrict__ lab,
                                                   float* __restrict__ out) {
    __shared__ float4 s_c[Kk * 8];
    __shared__ float  s_h[W1][Kk];
    __shared__ float  s_cnt[Kk];
    __shared__ float  red[3][W1];
    __shared__ int    s_flag;

    int tid = threadIdx.x;
    int w = tid >> 5;
    int lane = tid & 31;
    int sub = lane >> 3;
    int l8  = lane & 7;
    int b = blockIdx.x / BPB;

    for (int i = tid; i < Kk * 8; i += T1) {
        float cnt = g_counts[b * Kk + (i >> 3)];
        float inv = 1.f / fmaxf(cnt, 1.f);
        float4 s = g_sums4[b * Kk * 8 + i];
        s_c[i] = make_float4(s.x * inv, s.y * inv, s.z * inv, s.w * inv);
    }
    if (tid < Kk) s_cnt[tid] = g_counts[b * Kk + tid];
    for (int i = lane; i < Kk; i += 32) s_h[w][i] = 0.f;
    __syncthreads();

    int base = b * Nn + (blockIdx.x % BPB) * PPB;

    for (int p0 = w * 16; p0 < PPB; p0 += W1 * 16) {
        int gp0 = base + p0 + sub;
        // front-batched loads (MLP = 4x128B + labels)
        float4 v0 = emb4[(size_t)(gp0     ) * 8 + l8];
        float4 v1 = emb4[(size_t)(gp0 +  4) * 8 + l8];
        float4 v2 = emb4[(size_t)(gp0 +  8) * 8 + l8];
        float4 v3 = emb4[(size_t)(gp0 + 12) * 8 + l8];
        int k0 = lab[gp0];
        int k1 = lab[gp0 + 4];
        int k2 = lab[gp0 + 8];
        int k3 = lab[gp0 + 12];

        float4 c0 = s_c[k0 * 8 + l8];
        float4 c1 = s_c[k1 * 8 + l8];
        float4 c2 = s_c[k2 * 8 + l8];
        float4 c3 = s_c[k3 * 8 + l8];

        float dx, dy, dz, dw;
        dx = v0.x - c0.x; dy = v0.y - c0.y; dz = v0.z - c0.z; dw = v0.w - c0.w;
        float d2_0 = dx * dx + dy * dy + dz * dz + dw * dw;
        dx = v1.x - c1.x; dy = v1.y - c1.y; dz = v1.z - c1.z; dw = v1.w - c1.w;
        float d2_1 = dx * dx + dy * dy + dz * dz + dw * dw;
        dx = v2.x - c2.x; dy = v2.y - c2.y; dz = v2.z - c2.z; dw = v2.w - c2.w;
        float d2_2 = dx * dx + dy * dy + dz * dz + dw * dw;
        dx = v3.x - c3.x; dy = v3.y - c3.y; dz = v3.z - c3.z; dw = v3.w - c3.w;
        float d2_3 = dx * dx + dy * dy + dz * dz + dw * dw;

#pragma unroll
        for (int off = 1; off <= 4; off <<= 1) {
            d2_0 += __shfl_xor_sync(FULLM, d2_0, off);
            d2_1 += __shfl_xor_sync(FULLM, d2_1, off);
            d2_2 += __shfl_xor_sync(FULLM, d2_2, off);
            d2_3 += __shfl_xor_sync(FULLM, d2_3, off);
        }
        if (l8 == 0) {
            if (k0 > 0) { float h = sqrtf(fmaxf(d2_0, EPSX)) - DELTA_V; if (h > 0.f) atomicAdd(&s_h[w][k0], h); }
            if (k1 > 0) { float h = sqrtf(fmaxf(d2_1, EPSX)) - DELTA_V; if (h > 0.f) atomicAdd(&s_h[w][k1], h); }
            if (k2 > 0) { float h = sqrtf(fmaxf(d2_2, EPSX)) - DELTA_V; if (h > 0.f) atomicAdd(&s_h[w][k2], h); }
            if (k3 > 0) { float h = sqrtf(fmaxf(d2_3, EPSX)) - DELTA_V; if (h > 0.f) atomicAdd(&s_h[w][k3], h); }
        }
    }
    __syncthreads();

    for (int i = tid; i < Kk; i += T1) {
        float s = 0.f;
#pragma unroll
        for (int ww = 0; ww < W1; ww++) s += s_h[ww][i];
        atomicAdd(&g_hinge[b * Kk + i], s);
    }

    // ---- last-block-done: finalize batch b ----
    __threadfence();            // release our g_hinge contributions
    __syncthreads();
    if (tid == 0) {
        int done = atomicAdd(&g_ctr[b], 1);
        s_flag = (done == BPB - 1) ? 1 : 0;
    }
    __syncthreads();
    if (!s_flag) return;
    __threadfence();            // acquire: all blocks' g_hinge now visible

    float var_acc = 0.f, reg_acc = 0.f, pair_acc = 0.f;

    if (tid >= 1 && tid < Kk && s_cnt[tid] > 0.f) {
        int k = tid;
        var_acc = g_hinge[b * Kk + k] / s_cnt[k];
        float n2 = 0.f;
#pragma unroll
        for (int j = 0; j < 8; j++) {
            float4 c = s_c[k * 8 + j];
            n2 += c.x * c.x + c.y * c.y + c.z * c.z + c.w * c.w;
        }
        reg_acc = sqrtf(fmaxf(n2, EPSX));
    }

    for (int pi = tid; pi < Kk * Kk; pi += T1) {
        int i = pi / Kk, j = pi % Kk;
        if (i >= 1 && j > i && s_cnt[i] > 0.f && s_cnt[j] > 0.f) {
            float d2 = 0.f;
#pragma unroll
            for (int e = 0; e < 8; e++) {
                float4 a = s_c[i * 8 + e], bb = s_c[j * 8 + e];
                float ex = a.x - bb.x, ey = a.y - bb.y, ez = a.z - bb.z, ew = a.w - bb.w;
                d2 += ex * ex + ey * ey + ez * ez + ew * ew;
            }
            float cd = sqrtf(fmaxf(d2, EPSX));
            pair_acc += fmaxf(2.f * DELTA_D - cd, 0.f);
        }
    }

#pragma unroll
    for (int off = 16; off; off >>= 1) {
        var_acc  += __shfl_xor_sync(FULLM, var_acc, off);
        reg_acc  += __shfl_xor_sync(FULLM, reg_acc, off);
        pair_acc += __shfl_xor_sync(FULLM, pair_acc, off);
    }
    if (lane == 0) { red[0][w] = var_acc; red[1][w] = reg_acc; red[2][w] = pair_acc; }
    __syncthreads();

    if (tid == 0) {
        float var_s = 0.f, reg_s = 0.f, pair_s = 0.f;
#pragma unroll
        for (int ww = 0; ww < W1; ww++) {
            var_s += red[0][ww]; reg_s += red[1][ww]; pair_s += red[2][ww];
        }
        float ni = 0.f;
        for (int k = 1; k < Kk; k++) ni += (s_cnt[k] > 0.f) ? 1.f : 0.f;
        float var_t = var_s / fmaxf(ni, 1.f);
        float npairs = ni * (ni - 1.f) * 0.5f;
        float dist_t = pair_s / fmaxf(npairs, 1.f);
        float reg_t = reg_s / fmaxf(ni, 1.f);
        float pb = var_t + dist_t + GAMMA * reg_t;
        if (!(ni > 0.f)) pb = 0.f;
        atomicAdd(out, pb / (float)Bz);
    }
    __syncthreads();

    // ---- self-clean this batch's scratch for the next graph replay ----
    // (every consumer of batch b's scratch has already passed the counter)
    for (int i = tid; i < Kk * 8; i += T1)
        g_sums4[b * Kk * 8 + i] = make_float4(0.f, 0.f, 0.f, 0.f);
    for (int i = tid; i < Kk; i += T1) {
        g_counts[b * Kk + i] = 0.f;
        g_hinge[b * Kk + i] = 0.f;
    }
    if (tid == 0) g_ctr[b] = 0;
}

// ---------------------------------------------------------------------------
extern "C" void kernel_launch(void* const* d_in, const int* in_sizes, int n_in,
                              void* d_out, int out_size) {
    const float4* emb4 = (const float4*)d_in[0];
    const int* lab = (const int*)d_in[1];
    float* out = (float*)d_out;

    pass1_kernel<<<Bz * BPB, T1>>>(emb4, lab, out);
    pass2_kernel<<<Bz * BPB, T1>>>(emb4, lab, out);
}

// round 9
// speedup vs baseline: 1.9756x; 1.0398x over previous
#include <cuda_runtime.h>

#define Bz 8
#define Nn 65536
#define Ee 32
#define Kk 33
#define BPB 128            // blocks per batch
#define PPB (Nn / BPB)     // 512 points per block
#define T1 256
#define W1 (T1 / 32)

#define DELTA_V 0.5f
#define DELTA_D 1.5f
#define GAMMA 0.001f
#define EPSX 1e-12f

#define FULLM 0xFFFFFFFFu

// Scratch (allocation-free rule: __device__ globals, zero-init at load;
// self-cleaned at end of each run so graph replays stay deterministic).
__device__ float4 g_sums4[Bz * Kk * 8];   // [b][k][e/4]
__device__ float  g_counts[Bz * Kk];
__device__ float  g_hinge[Bz * Kk];
__device__ int    g_ctr[Bz];

// L2 evict_last via access policy (sm_103a ptxas rejects the bare
// .L2::evict_last qualifier below v8.b32; cache_hint form takes any width).
// Keeps the 66MB emb+label working set resident in the 126MB L2 so pass2
// (and graph-replay steady state) hits L2 instead of DRAM.
__device__ __forceinline__ unsigned long long mk_evict_last_policy() {
    unsigned long long pol;
    asm("createpolicy.fractional.L2::evict_last.b64 %0, 1.0;" : "=l"(pol));
    return pol;
}
__device__ __forceinline__ float4 ldg_el4(const float4* p, unsigned long long pol) {
    float4 v;
    asm("ld.global.L2::cache_hint.v4.f32 {%0,%1,%2,%3}, [%4], %5;"
        : "=f"(v.x), "=f"(v.y), "=f"(v.z), "=f"(v.w) : "l"(p), "l"(pol));
    return v;
}
__device__ __forceinline__ int ldg_eli(const int* p, unsigned long long pol) {
    int v;
    asm("ld.global.L2::cache_hint.b32 %0, [%1], %2;" : "=r"(v) : "l"(p), "l"(pol));
    return v;
}

// ---------------------------------------------------------------------------
// Pass 1: per-(b,k) embedding sums + counts.
// float4 / 8-lanes-per-point, unroll-2. Per-warp PRIVATE shared accumulators;
// label collisions among the 4 points of a half handled by serialization.
// ---------------------------------------------------------------------------
__global__ void __launch_bounds__(T1) pass1_kernel(const float4* __restrict__ emb4,
                                                   const int* __restrict__ lab,
                                                   float* __restrict__ out) {
    __shared__ float4 s_sum[W1][Kk * 8];
    __shared__ float  s_cnt[W1][Kk];

    int tid = threadIdx.x;
    int w = tid >> 5;
    int lane = tid & 31;
    int sub = lane >> 3;     // which of 4 points in a half
    int l8  = lane & 7;      // float4 slot within the point
    unsigned long long pol = mk_evict_last_policy();

    if (blockIdx.x == 0 && tid == 0) out[0] = 0.f;   // ordered before pass2

    for (int i = lane; i < Kk * 8; i += 32) s_sum[w][i] = make_float4(0.f, 0.f, 0.f, 0.f);
    for (int i = lane; i < Kk; i += 32) s_cnt[w][i] = 0.f;
    __syncwarp();

    int b = blockIdx.x / BPB;
    int base = b * Nn + (blockIdx.x % BPB) * PPB;

    for (int p0 = w * 8; p0 < PPB; p0 += W1 * 8) {
        int gp0 = base + p0 + sub;
        int gp1 = gp0 + 4;
        // front-batched loads (MLP = 2x128B + labels)
        float4 v0 = ldg_el4(emb4 + (size_t)gp0 * 8 + l8, pol);
        float4 v1 = ldg_el4(emb4 + (size_t)gp1 * 8 + l8, pol);
        int k0 = ldg_eli(lab + gp0, pol);
        int k1 = ldg_eli(lab + gp1, pol);

#pragma unroll
        for (int h = 0; h < 2; h++) {
            float4 v = h ? v1 : v0;
            int k = h ? k1 : k0;
            unsigned m = __match_any_sync(FULLM, k);
            bool all_distinct = __all_sync(FULLM, __popc(m) == 8);
            int idx = k * 8 + l8;
            if (all_distinct) {                     // ~83% of halves
                float4 a = s_sum[w][idx];
                a.x += v.x; a.y += v.y; a.z += v.z; a.w += v.w;
                s_sum[w][idx] = a;
                if (l8 == 0) s_cnt[w][k] += 1.f;
            } else {                                // serialize the 4 points
#pragma unroll
                for (int s = 0; s < 4; s++) {
                    if (sub == s) {
                        float4 a = s_sum[w][idx];
                        a.x += v.x; a.y += v.y; a.z += v.z; a.w += v.w;
                        s_sum[w][idx] = a;
                        if (l8 == 0) s_cnt[w][k] += 1.f;
                    }
                    __syncwarp();
                }
            }
            __syncwarp();   // order cross-lane shared RMW between halves/iters
        }
    }
    __syncthreads();

    // merge warp copies -> global (spread atomics over 8448 addrs, cheap)
    const float* flat[W1];
#pragma unroll
    for (int ww = 0; ww < W1; ww++) flat[ww] = (const float*)s_sum[ww];
    float* gs = (float*)g_sums4;
    for (int i = tid; i < Kk * Ee; i += T1) {
        float s = 0.f;
#pragma unroll
        for (int ww = 0; ww < W1; ww++) s += flat[ww][i];
        atomicAdd(gs + b * Kk * Ee + i, s);
    }
    for (int i = tid; i < Kk; i += T1) {
        float s = 0.f;
#pragma unroll
        for (int ww = 0; ww < W1; ww++) s += s_cnt[ww][i];
        atomicAdd(&g_counts[b * Kk + i], s);
    }
}

// ---------------------------------------------------------------------------
// Pass 2: per-point hinge(||x - c_label|| - delta_v), summed per (b,k).
// unroll-4 x software-pipelined (next iteration's 4 LDG.128 + labels issued
// before processing the current one => ~8 loads in flight per warp).
// Last block of each batch runs the K=33 finalize, adds into out, and
// re-zeroes this batch's scratch for the next graph replay.
// ---------------------------------------------------------------------------
__global__ void __launch_bounds__(T1) pass2_kernel(const float4* __restrict__ emb4,
                                                   const int* __restrict__ lab,
                                                   float* __restrict__ out) {
    __shared__ float4 s_c[Kk * 8];
    __shared__ float  s_h[W1][Kk];
    __shared__ float  s_cnt[Kk];
    __shared__ float  red[3][W1];
    __shared__ int    s_flag;

    int tid = threadIdx.x;
    int w = tid >> 5;
    int lane = tid & 31;
    int sub = lane >> 3;
    int l8  = lane & 7;
    int b = blockIdx.x / BPB;
    unsigned long long pol = mk_evict_last_policy();

    for (int i = tid; i < Kk * 8; i += T1) {
        float cnt = g_counts[b * Kk + (i >> 3)];
        float inv = 1.f / fmaxf(cnt, 1.f);
        float4 s = g_sums4[b * Kk * 8 + i];
        s_c[i] = make_float4(s.x * inv, s.y * inv, s.z * inv, s.w * inv);
    }
    if (tid < Kk) s_cnt[tid] = g_counts[b * Kk + tid];
    for (int i = lane; i < Kk; i += 32) s_h[w][i] = 0.f;
    __syncthreads();

    int base = b * Nn + (blockIdx.x % BPB) * PPB;
    const int STRIDE = W1 * 16;               // 128 points per warp-iter round
    const int NIT = PPB / STRIDE;             // exactly 4 iterations per warp

    int gp = base + w * 16 + sub;
    // prologue loads (iteration 0)
    float4 v0 = ldg_el4(emb4 + (size_t)(gp     ) * 8 + l8, pol);
    float4 v1 = ldg_el4(emb4 + (size_t)(gp +  4) * 8 + l8, pol);
    float4 v2 = ldg_el4(emb4 + (size_t)(gp +  8) * 8 + l8, pol);
    float4 v3 = ldg_el4(emb4 + (size_t)(gp + 12) * 8 + l8, pol);
    int k0 = ldg_eli(lab + gp, pol);
    int k1 = ldg_eli(lab + gp + 4, pol);
    int k2 = ldg_eli(lab + gp + 8, pol);
    int k3 = ldg_eli(lab + gp + 12, pol);

#pragma unroll
    for (int it = 0; it < NIT; it++) {
        // prefetch next iteration before touching dependent centers
        float4 n0, n1, n2, n3; int m0, m1, m2, m3;
        if (it + 1 < NIT) {
            int ng = gp + STRIDE;
            n0 = ldg_el4(emb4 + (size_t)(ng     ) * 8 + l8, pol);
            n1 = ldg_el4(emb4 + (size_t)(ng +  4) * 8 + l8, pol);
            n2 = ldg_el4(emb4 + (size_t)(ng +  8) * 8 + l8, pol);
            n3 = ldg_el4(emb4 + (size_t)(ng + 12) * 8 + l8, pol);
            m0 = ldg_eli(lab + ng, pol);
            m1 = ldg_eli(lab + ng + 4, pol);
            m2 = ldg_eli(lab + ng + 8, pol);
            m3 = ldg_eli(lab + ng + 12, pol);
        }

        float4 c0 = s_c[k0 * 8 + l8];
        float4 c1 = s_c[k1 * 8 + l8];
        float4 c2 = s_c[k2 * 8 + l8];
        float4 c3 = s_c[k3 * 8 + l8];

        float dx, dy, dz, dw;
        dx = v0.x - c0.x; dy = v0.y - c0.y; dz = v0.z - c0.z; dw = v0.w - c0.w;
        float d2_0 = dx * dx + dy * dy + dz * dz + dw * dw;
        dx = v1.x - c1.x; dy = v1.y - c1.y; dz = v1.z - c1.z; dw = v1.w - c1.w;
        float d2_1 = dx * dx + dy * dy + dz * dz + dw * dw;
        dx = v2.x - c2.x; dy = v2.y - c2.y; dz = v2.z - c2.z; dw = v2.w - c2.w;
        float d2_2 = dx * dx + dy * dy + dz * dz + dw * dw;
        dx = v3.x - c3.x; dy = v3.y - c3.y; dz = v3.z - c3.z; dw = v3.w - c3.w;
        float d2_3 = dx * dx + dy * dy + dz * dz + dw * dw;

#pragma unroll
        for (int off = 1; off <= 4; off <<= 1) {
            d2_0 += __shfl_xor_sync(FULLM, d2_0, off);
            d2_1 += __shfl_xor_sync(FULLM, d2_1, off);
            d2_2 += __shfl_xor_sync(FULLM, d2_2, off);
            d2_3 += __shfl_xor_sync(FULLM, d2_3, off);
        }
        if (l8 == 0) {
            if (k0 > 0) { float h = sqrtf(fmaxf(d2_0, EPSX)) - DELTA_V; if (h > 0.f) atomicAdd(&s_h[w][k0], h); }
            if (k1 > 0) { float h = sqrtf(fmaxf(d2_1, EPSX)) - DELTA_V; if (h > 0.f) atomicAdd(&s_h[w][k1], h); }
            if (k2 > 0) { float h = sqrtf(fmaxf(d2_2, EPSX)) - DELTA_V; if (h > 0.f) atomicAdd(&s_h[w][k2], h); }
            if (k3 > 0) { float h = sqrtf(fmaxf(d2_3, EPSX)) - DELTA_V; if (h > 0.f) atomicAdd(&s_h[w][k3], h); }
        }

        v0 = n0; v1 = n1; v2 = n2; v3 = n3;
        k0 = m0; k1 = m1; k2 = m2; k3 = m3;
        gp += STRIDE;
    }
    __syncthreads();

    for (int i = tid; i < Kk; i += T1) {
        float s = 0.f;
#pragma unroll
        for (int ww = 0; ww < W1; ww++) s += s_h[ww][i];
        atomicAdd(&g_hinge[b * Kk + i], s);
    }

    // ---- last-block-done: finalize batch b ----
    __threadfence();            // release our g_hinge contributions
    __syncthreads();
    if (tid == 0) {
        int done = atomicAdd(&g_ctr[b], 1);
        s_flag = (done == BPB - 1) ? 1 : 0;
    }
    __syncthreads();
    if (!s_flag) return;
    __threadfence();            // acquire: all blocks' g_hinge now visible

    float var_acc = 0.f, reg_acc = 0.f, pair_acc = 0.f;

    if (tid >= 1 && tid < Kk && s_cnt[tid] > 0.f) {
        int k = tid;
        var_acc = g_hinge[b * Kk + k] / s_cnt[k];
        float n2 = 0.f;
#pragma unroll
        for (int j = 0; j < 8; j++) {
            float4 c = s_c[k * 8 + j];
            n2 += c.x * c.x + c.y * c.y + c.z * c.z + c.w * c.w;
        }
        reg_acc = sqrtf(fmaxf(n2, EPSX));
    }

    for (int pi = tid; pi < Kk * Kk; pi += T1) {
        int i = pi / Kk, j = pi % Kk;
        if (i >= 1 && j > i && s_cnt[i] > 0.f && s_cnt[j] > 0.f) {
            float d2 = 0.f;
#pragma unroll
            for (int e = 0; e < 8; e++) {
                float4 a = s_c[i * 8 + e], bb = s_c[j * 8 + e];
                float ex = a.x - bb.x, ey = a.y - bb.y, ez = a.z - bb.z, ew = a.w - bb.w;
                d2 += ex * ex + ey * ey + ez * ez + ew * ew;
            }
            float cd = sqrtf(fmaxf(d2, EPSX));
            pair_acc += fmaxf(2.f * DELTA_D - cd, 0.f);
        }
    }

#pragma unroll
    for (int off = 16; off; off >>= 1) {
        var_acc  += __shfl_xor_sync(FULLM, var_acc, off);
        reg_acc  += __shfl_xor_sync(FULLM, reg_acc, off);
        pair_acc += __shfl_xor_sync(FULLM, pair_acc, off);
    }
    if (lane == 0) { red[0][w] = var_acc; red[1][w] = reg_acc; red[2][w] = pair_acc; }
    __syncthreads();

    if (tid == 0) {
        float var_s = 0.f, reg_s = 0.f, pair_s = 0.f;
#pragma unroll
        for (int ww = 0; ww < W1; ww++) {
            var_s += red[0][ww]; reg_s += red[1][ww]; pair_s += red[2][ww];
        }
        float ni = 0.f;
        for (int k = 1; k < Kk; k++) ni += (s_cnt[k] > 0.f) ? 1.f : 0.f;
        float var_t = var_s / fmaxf(ni, 1.f);
        float npairs = ni * (ni - 1.f) * 0.5f;
        float dist_t = pair_s / fmaxf(npairs, 1.f);
        float reg_t = reg_s / fmaxf(ni, 1.f);
        float pb = var_t + dist_t + GAMMA * reg_t;
        if (!(ni > 0.f)) pb = 0.f;
        atomicAdd(out, pb / (float)Bz);
    }
    __syncthreads();

    // ---- self-clean this batch's scratch for the next graph replay ----
    for (int i = tid; i < Kk * 8; i += T1)
        g_sums4[b * Kk * 8 + i] = make_float4(0.f, 0.f, 0.f, 0.f);
    for (int i = tid; i < Kk; i += T1) {
        g_counts[b * Kk + i] = 0.f;
        g_hinge[b * Kk + i] = 0.f;
    }
    if (tid == 0) g_ctr[b] = 0;
}

// ---------------------------------------------------------------------------
extern "C" void kernel_launch(void* const* d_in, const int* in_sizes, int n_in,
                              void* d_out, int out_size) {
    const float4* emb4 = (const float4*)d_in[0];
    const int* lab = (const int*)d_in[1];
    float* out = (float*)d_out;

    pass1_kernel<<<Bz * BPB, T1>>>(emb4, lab, out);
    pass2_kernel<<<Bz * BPB, T1>>>(emb4, lab, out);
}

// round 10
// speedup vs baseline: 2.1037x; 1.0648x over previous
#include <cuda_runtime.h>

#define Bz 8
#define Nn 65536
#define Ee 32
#define Kk 33
#define BPB 32             // blocks per batch
#define PPB 2048           // points per block
#define TT 512
#define WW (TT / 32)       // 16 warps
#define GRID (Bz * BPB)    // 256 blocks, all resident at 2 blocks/SM

#define DELTA_V 0.5f
#define DELTA_D 1.5f
#define GAMMA 0.001f
#define EPSX 1e-12f
#define FULLM 0xFFFFFFFFu

// Scratch (allocation-free rule: __device__ globals, zero-init at load;
// self-cleaned at end of each run so graph replays stay deterministic).
__device__ float4 g_sums4[Bz * Kk * 8];   // [b][k][e/4]
__device__ float  g_counts[Bz * Kk];
__device__ float  g_hinge[Bz * Kk];
__device__ int    g_ctr[Bz];
__device__ unsigned int g_sync;           // monotone ticket counter (no reset)

// evict_last via cache_hint (bare qualifier rejected below v8.b32 on sm_103a)
__device__ __forceinline__ unsigned long long mk_pol() {
    unsigned long long pol;
    asm("createpolicy.fractional.L2::evict_last.b64 %0, 1.0;" : "=l"(pol));
    return pol;
}
__device__ __forceinline__ float4 ldg_el4(const float4* p, unsigned long long pol) {
    float4 v;
    asm("ld.global.L2::cache_hint.v4.f32 {%0,%1,%2,%3}, [%4], %5;"
        : "=f"(v.x), "=f"(v.y), "=f"(v.z), "=f"(v.w) : "l"(p), "l"(pol));
    return v;
}
__device__ __forceinline__ int ldg_eli(const int* p, unsigned long long pol) {
    int v;
    asm("ld.global.L2::cache_hint.b32 %0, [%1], %2;" : "=r"(v) : "l"(p), "l"(pol));
    return v;
}

// ---------------------------------------------------------------------------
// Fused persistent kernel: phase 1 (sums/counts) -> grid ticket sync ->
// phase 2 (hinge) -> per-batch finalize (last-block-done).
// ---------------------------------------------------------------------------
__global__ void __launch_bounds__(TT, 2) fused_kernel(const float4* __restrict__ emb4,
                                                      const int* __restrict__ lab,
                                                      float* __restrict__ out) {
    // dynamic: per-warp phase-1 accumulators (16 x 33 x 8 float4 + 16 x 33 f)
    extern __shared__ char dyn[];
    float4 (*s_sum)[Kk * 8] = (float4 (*)[Kk * 8])dyn;
    float  (*s_cnt1)[Kk]    = (float (*)[Kk])(dyn + (size_t)WW * Kk * 8 * sizeof(float4));

    // static: phase-2 working set
    __shared__ float4 s_c[Kk * 8];
    __shared__ float  s_h[WW][Kk];
    __shared__ float  s_cnt[Kk];
    __shared__ float  red[3][WW];
    __shared__ int    s_flag;

    int tid = threadIdx.x;
    int w = tid >> 5;
    int lane = tid & 31;
    int sub = lane >> 3;
    int l8  = lane & 7;
    unsigned long long pol = mk_pol();

    int b = blockIdx.x / BPB;
    int base = b * Nn + (blockIdx.x % BPB) * PPB;

    // ================= PHASE 1: segment sums + counts =================
    for (int i = lane; i < Kk * 8; i += 32) s_sum[w][i] = make_float4(0.f, 0.f, 0.f, 0.f);
    for (int i = lane; i < Kk; i += 32) s_cnt1[w][i] = 0.f;
    __syncwarp();

    for (int p0 = w * 8; p0 < PPB; p0 += WW * 8) {
        int gp0 = base + p0 + sub;
        int gp1 = gp0 + 4;
        float4 v0 = ldg_el4(emb4 + (size_t)gp0 * 8 + l8, pol);
        float4 v1 = ldg_el4(emb4 + (size_t)gp1 * 8 + l8, pol);
        int k0 = ldg_eli(lab + gp0, pol);
        int k1 = ldg_eli(lab + gp1, pol);

#pragma unroll
        for (int h = 0; h < 2; h++) {
            float4 v = h ? v1 : v0;
            int k = h ? k1 : k0;
            unsigned m = __match_any_sync(FULLM, k);
            bool all_distinct = __all_sync(FULLM, __popc(m) == 8);
            int idx = k * 8 + l8;
            if (all_distinct) {
                float4 a = s_sum[w][idx];
                a.x += v.x; a.y += v.y; a.z += v.z; a.w += v.w;
                s_sum[w][idx] = a;
                if (l8 == 0) s_cnt1[w][k] += 1.f;
            } else {
#pragma unroll
                for (int s = 0; s < 4; s++) {
                    if (sub == s) {
                        float4 a = s_sum[w][idx];
                        a.x += v.x; a.y += v.y; a.z += v.z; a.w += v.w;
                        s_sum[w][idx] = a;
                        if (l8 == 0) s_cnt1[w][k] += 1.f;
                    }
                    __syncwarp();
                }
            }
            __syncwarp();
        }
    }
    __syncthreads();

    // merge warp copies -> global (spread atomics)
    float* gs = (float*)g_sums4;
    const float* flat0 = (const float*)dyn;
    const size_t wstride = (size_t)Kk * 8 * 4;     // floats per warp copy
    for (int i = tid; i < Kk * Ee; i += TT) {
        float s = 0.f;
#pragma unroll
        for (int ww = 0; ww < WW; ww++) s += flat0[ww * wstride + i];
        atomicAdd(gs + b * Kk * Ee + i, s);
    }
    for (int i = tid; i < Kk; i += TT) {
        float s = 0.f;
#pragma unroll
        for (int ww = 0; ww < WW; ww++) s += s_cnt1[ww][i];
        atomicAdd(&g_counts[b * Kk + i], s);
    }

    // ================= GRID TICKET SYNC (all 256 blocks resident) ===========
    __threadfence();             // release our phase-1 contributions
    __syncthreads();
    if (tid == 0) {
        if (blockIdx.x == 0) {   // zero output BEFORE arriving (ordered by fence)
            *out = 0.f;
            __threadfence();
        }
        unsigned t = atomicAdd(&g_sync, 1u);
        unsigned target = (t / GRID + 1u) * GRID;
        unsigned v;
        do {
            asm volatile("ld.acquire.gpu.u32 %0, [%1];" : "=r"(v) : "l"(&g_sync));
            if (v < target) __nanosleep(64);
        } while (v < target);
    }
    __syncthreads();

    // ================= PHASE 2: per-point hinge =================
    for (int i = tid; i < Kk * 8; i += TT) {
        float cnt = g_counts[b * Kk + (i >> 3)];
        float inv = 1.f / fmaxf(cnt, 1.f);
        float4 s = g_sums4[b * Kk * 8 + i];
        s_c[i] = make_float4(s.x * inv, s.y * inv, s.z * inv, s.w * inv);
    }
    if (tid < Kk) s_cnt[tid] = g_counts[b * Kk + tid];
    for (int i = lane; i < Kk; i += 32) s_h[w][i] = 0.f;
    __syncthreads();

    for (int p0 = w * 16; p0 < PPB; p0 += WW * 16) {
        int gp = base + p0 + sub;
        float4 v0 = ldg_el4(emb4 + (size_t)(gp     ) * 8 + l8, pol);
        float4 v1 = ldg_el4(emb4 + (size_t)(gp +  4) * 8 + l8, pol);
        float4 v2 = ldg_el4(emb4 + (size_t)(gp +  8) * 8 + l8, pol);
        float4 v3 = ldg_el4(emb4 + (size_t)(gp + 12) * 8 + l8, pol);
        int k0 = ldg_eli(lab + gp, pol);
        int k1 = ldg_eli(lab + gp + 4, pol);
        int k2 = ldg_eli(lab + gp + 8, pol);
        int k3 = ldg_eli(lab + gp + 12, pol);

        float4 c0 = s_c[k0 * 8 + l8];
        float4 c1 = s_c[k1 * 8 + l8];
        float4 c2 = s_c[k2 * 8 + l8];
        float4 c3 = s_c[k3 * 8 + l8];

        float dx, dy, dz, dw;
        dx = v0.x - c0.x; dy = v0.y - c0.y; dz = v0.z - c0.z; dw = v0.w - c0.w;
        float d2_0 = dx * dx + dy * dy + dz * dz + dw * dw;
        dx = v1.x - c1.x; dy = v1.y - c1.y; dz = v1.z - c1.z; dw = v1.w - c1.w;
        float d2_1 = dx * dx + dy * dy + dz * dz + dw * dw;
        dx = v2.x - c2.x; dy = v2.y - c2.y; dz = v2.z - c2.z; dw = v2.w - c2.w;
        float d2_2 = dx * dx + dy * dy + dz * dz + dw * dw;
        dx = v3.x - c3.x; dy = v3.y - c3.y; dz = v3.z - c3.z; dw = v3.w - c3.w;
        float d2_3 = dx * dx + dy * dy + dz * dz + dw * dw;

#pragma unroll
        for (int off = 1; off <= 4; off <<= 1) {
            d2_0 += __shfl_xor_sync(FULLM, d2_0, off);
            d2_1 += __shfl_xor_sync(FULLM, d2_1, off);
            d2_2 += __shfl_xor_sync(FULLM, d2_2, off);
            d2_3 += __shfl_xor_sync(FULLM, d2_3, off);
        }
        if (l8 == 0) {
            if (k0 > 0) { float h = sqrtf(fmaxf(d2_0, EPSX)) - DELTA_V; if (h > 0.f) atomicAdd(&s_h[w][k0], h); }
            if (k1 > 0) { float h = sqrtf(fmaxf(d2_1, EPSX)) - DELTA_V; if (h > 0.f) atomicAdd(&s_h[w][k1], h); }
            if (k2 > 0) { float h = sqrtf(fmaxf(d2_2, EPSX)) - DELTA_V; if (h > 0.f) atomicAdd(&s_h[w][k2], h); }
            if (k3 > 0) { float h = sqrtf(fmaxf(d2_3, EPSX)) - DELTA_V; if (h > 0.f) atomicAdd(&s_h[w][k3], h); }
        }
    }
    __syncthreads();

    for (int i = tid; i < Kk; i += TT) {
        float s = 0.f;
#pragma unroll
        for (int ww = 0; ww < WW; ww++) s += s_h[ww][i];
        atomicAdd(&g_hinge[b * Kk + i], s);
    }

    // ================= per-batch finalize: last-block-done =================
    __threadfence();
    __syncthreads();
    if (tid == 0) {
        int done = atomicAdd(&g_ctr[b], 1);
        s_flag = (done == BPB - 1) ? 1 : 0;
    }
    __syncthreads();
    if (!s_flag) return;
    __threadfence();

    float var_acc = 0.f, reg_acc = 0.f, pair_acc = 0.f;

    if (tid >= 1 && tid < Kk && s_cnt[tid] > 0.f) {
        int k = tid;
        var_acc = g_hinge[b * Kk + k] / s_cnt[k];
        float n2 = 0.f;
#pragma unroll
        for (int j = 0; j < 8; j++) {
            float4 c = s_c[k * 8 + j];
            n2 += c.x * c.x + c.y * c.y + c.z * c.z + c.w * c.w;
        }
        reg_acc = sqrtf(fmaxf(n2, EPSX));
    }

    for (int pi = tid; pi < Kk * Kk; pi += TT) {
        int i = pi / Kk, j = pi % Kk;
        if (i >= 1 && j > i && s_cnt[i] > 0.f && s_cnt[j] > 0.f) {
            float d2 = 0.f;
#pragma unroll
            for (int e = 0; e < 8; e++) {
                float4 a = s_c[i * 8 + e], bb = s_c[j * 8 + e];
                float ex = a.x - bb.x, ey = a.y - bb.y, ez = a.z - bb.z, ew = a.w - bb.w;
                d2 += ex * ex + ey * ey + ez * ez + ew * ew;
            }
            float cd = sqrtf(fmaxf(d2, EPSX));
            pair_acc += fmaxf(2.f * DELTA_D - cd, 0.f);
        }
    }

#pragma unroll
    for (int off = 16; off; off >>= 1) {
        var_acc  += __shfl_xor_sync(FULLM, var_acc, off);
        reg_acc  += __shfl_xor_sync(FULLM, reg_acc, off);
        pair_acc += __shfl_xor_sync(FULLM, pair_acc, off);
    }
    if (lane == 0) { red[0][w] = var_acc; red[1][w] = reg_acc; red[2][w] = pair_acc; }
    __syncthreads();

    if (tid == 0) {
        float var_s = 0.f, reg_s = 0.f, pair_s = 0.f;
#pragma unroll
        for (int ww = 0; ww < WW; ww++) {
            var_s += red[0][ww]; reg_s += red[1][ww]; pair_s += red[2][ww];
        }
        float ni = 0.f;
        for (int k = 1; k < Kk; k++) ni += (s_cnt[k] > 0.f) ? 1.f : 0.f;
        float var_t = var_s / fmaxf(ni, 1.f);
        float npairs = ni * (ni - 1.f) * 0.5f;
        float dist_t = pair_s / fmaxf(npairs, 1.f);
        float reg_t = reg_s / fmaxf(ni, 1.f);
        float pb = var_t + dist_t + GAMMA * reg_t;
        if (!(ni > 0.f)) pb = 0.f;
        atomicAdd(out, pb / (float)Bz);
    }
    __syncthreads();

    // self-clean this batch's scratch for the next graph replay
    for (int i = tid; i < Kk * 8; i += TT)
        g_sums4[b * Kk * 8 + i] = make_float4(0.f, 0.f, 0.f, 0.f);
    for (int i = tid; i < Kk; i += TT) {
        g_counts[b * Kk + i] = 0.f;
        g_hinge[b * Kk + i] = 0.f;
    }
    if (tid == 0) g_ctr[b] = 0;
}

// ---------------------------------------------------------------------------
extern "C" void kernel_launch(void* const* d_in, const int* in_sizes, int n_in,
                              void* d_out, int out_size) {
    const float4* emb4 = (const float4*)d_in[0];
    const int* lab = (const int*)d_in[1];
    float* out = (float*)d_out;

    const int dynBytes = WW * Kk * 8 * sizeof(float4) + WW * Kk * sizeof(float); // ~69.7KB
    static int attr_set = 0;
    if (!attr_set) {
        cudaFuncSetAttribute(fused_kernel, cudaFuncAttributeMaxDynamicSharedMemorySize, dynBytes);
        attr_set = 1;
    }
    fused_kernel<<<GRID, TT, dynBytes>>>(emb4, lab, out);
}